// round 1
// baseline (speedup 1.0000x reference)
#include <cuda_runtime.h>
#include <cuda_bf16.h>

#define NBINS 64

// out[i] = bins[ clip(searchsorted_right(bins, max(logit(x), bins[0])) - 1, 0, 63) ]
// (straight-through estimator is numerically just the bin edge value)

__device__ __forceinline__ float bucket_one(float x, const float* __restrict__ sb) {
    const float inv_step = 63.0f / 12.0f;   // uniform linspace(-6, 6, 64)

    // ---- fast path: __logf (MUFU.LG2-based) ----
    float s    = __logf(x) - __logf(1.0f - x);
    float sbar = fmaxf(s, sb[0]);
    float u    = (sbar + 6.0f) * inv_step;
    float fu   = floorf(u);
    float frac = u - fu;

    // ---- slow path: within 6e-4 bin-widths of an edge -> recompute with
    //      accurate logf, exactly mirroring reference log(x) - log(1-x) ----
    if (frac < 6.0e-4f || frac > 1.0f - 6.0e-4f) {
        s    = logf(x) - logf(1.0f - x);
        sbar = fmaxf(s, sb[0]);
        u    = (sbar + 6.0f) * inv_step;
        fu   = floorf(u);
    }

    int idx = (int)fu;
    idx = idx < 0 ? 0 : (idx > 63 ? 63 : idx);

    // ---- exact fixup against the real bin edges (searchsorted-right) ----
    float e = sb[idx];
    if (sbar < e) {                      // can only fire for idx >= 1 (sbar >= sb[0])
        idx -= 1;
        e = sb[idx];
    } else if (idx < 63 && sbar >= sb[idx + 1]) {
        idx += 1;
        e = sb[idx];
    }
    return e;
}

__global__ __launch_bounds__(256)
void logodds_discretize_kernel(const float* __restrict__ Xs,
                               const float* __restrict__ bins,
                               float* __restrict__ out,
                               int n) {
    __shared__ float sb[NBINS];
    if (threadIdx.x < NBINS) sb[threadIdx.x] = bins[threadIdx.x];
    __syncthreads();

    int n4 = n >> 2;                     // number of full float4s
    int i  = blockIdx.x * blockDim.x + threadIdx.x;

    if (i < n4) {
        float4 x = reinterpret_cast<const float4*>(Xs)[i];
        float4 r;
        r.x = bucket_one(x.x, sb);
        r.y = bucket_one(x.y, sb);
        r.z = bucket_one(x.z, sb);
        r.w = bucket_one(x.w, sb);
        reinterpret_cast<float4*>(out)[i] = r;
    }

    // scalar tail (N is divisible by 4 for this problem, but stay robust)
    int tail_start = n4 << 2;
    int t = tail_start + i;
    if (i < (n - tail_start)) {
        out[t] = bucket_one(Xs[t], sb);
    }
}

extern "C" void kernel_launch(void* const* d_in, const int* in_sizes, int n_in,
                              void* d_out, int out_size) {
    const float* Xs   = (const float*)d_in[0];
    const float* bins = (const float*)d_in[1];
    float* out        = (float*)d_out;
    int n = in_sizes[0];

    int n4      = (n + 3) >> 2;
    int threads = 256;
    int blocks  = (n4 + threads - 1) / threads;
    if (blocks < 1) blocks = 1;

    logodds_discretize_kernel<<<blocks, threads>>>(Xs, bins, out, n);
}

// round 2
// speedup vs baseline: 1.1901x; 1.1901x over previous
#include <cuda_runtime.h>
#include <cuda_bf16.h>

#define NBINS 64
#define TPB   256
#define QPT   2      // float4 quads per thread (8 elements/thread)

// out[i] = bins[ clip(searchsorted_right(bins, max(logit(x), bins[0])) - 1, 0, 63) ]
// Straight-through estimator is numerically just the selected bin-edge value.
//
// Fast path: bins = linspace(-6, 6, 64) is uniform, step 12/63. So
//   u = (s + 6) * 63/12 = (lg2(x) - lg2(1-x)) * (ln2 * 63/12) + 31.5
// and idx = floor(clamp(u, 0, 63)) — the clamp realizes both max(s, bins[0])
// and the index clip. Only elements within 3e-4 of an integer boundary of u
// (where __log2f's ~2e-5 error could flip the bin) take the exact slow path.

__device__ __forceinline__ int slow_idx(float x, float om, const float* __restrict__ sb) {
    // Bit-exact reproduction of the reference: libdevice logf == XLA log.
    float s    = logf(x) - logf(om);
    float sbar = fmaxf(s, sb[0]);
    float uu   = (sbar + 6.0f) * (63.0f / 12.0f);
    int i = (int)floorf(uu);
    i = i < 0 ? 0 : (i > 63 ? 63 : i);
    // exact searchsorted-right fixup against the true bin edges
    if (sbar < sb[i])                       i -= 1;
    else if (i < 63 && sbar >= sb[i + 1])   i += 1;
    return i;
}

__device__ __forceinline__ float bucket(float x, const float* __restrict__ sb) {
    const float KU = 0.6931471805599453f * (63.0f / 12.0f);  // ln2 * 5.25
    float om = 1.0f - x;
    float u  = fmaf(__log2f(x) - __log2f(om), KU, 31.5f);
    float r  = u - rintf(u);
    int idx;
    if (fabsf(r) < 3.0e-4f) {            // rare (~6e-4 of elements)
        idx = slow_idx(x, om, sb);
    } else {
        float uc = fminf(fmaxf(u, 0.0f), 63.0f);
        idx = (int)uc;                   // trunc == floor since uc >= 0
    }
    return sb[idx];
}

__global__ __launch_bounds__(TPB)
void logodds_discretize_kernel(const float* __restrict__ Xs,
                               const float* __restrict__ bins,
                               float* __restrict__ out,
                               int n) {
    __shared__ float sb[NBINS];
    if (threadIdx.x < NBINS) sb[threadIdx.x] = bins[threadIdx.x];
    __syncthreads();

    const float4* X4 = reinterpret_cast<const float4*>(Xs);
    float4*       O4 = reinterpret_cast<float4*>(out);
    int n4 = n >> 2;

    int i0 = blockIdx.x * (TPB * QPT) + threadIdx.x;
    int i1 = i0 + TPB;

    bool v0 = i0 < n4;
    bool v1 = i1 < n4;

    // front-batch both loads for MLP
    float4 a, b;
    if (v0) a = X4[i0];
    if (v1) b = X4[i1];

    if (v0) {
        float4 r;
        r.x = bucket(a.x, sb);
        r.y = bucket(a.y, sb);
        r.z = bucket(a.z, sb);
        r.w = bucket(a.w, sb);
        O4[i0] = r;
    }
    if (v1) {
        float4 r;
        r.x = bucket(b.x, sb);
        r.y = bucket(b.y, sb);
        r.z = bucket(b.z, sb);
        r.w = bucket(b.w, sb);
        O4[i1] = r;
    }

    // scalar tail (n % 4), handled by block 0 / first threads
    int tail_start = n4 << 2;
    int trem = n - tail_start;
    if (blockIdx.x == 0 && (int)threadIdx.x < trem) {
        int t = tail_start + threadIdx.x;
        out[t] = bucket(Xs[t], sb);
    }
}

extern "C" void kernel_launch(void* const* d_in, const int* in_sizes, int n_in,
                              void* d_out, int out_size) {
    const float* Xs   = (const float*)d_in[0];
    const float* bins = (const float*)d_in[1];
    float* out        = (float*)d_out;
    int n = in_sizes[0];

    int n4     = n >> 2;
    int per_blk = TPB * QPT;
    int blocks  = (n4 + per_blk - 1) / per_blk;
    if (blocks < 1) blocks = 1;

    logodds_discretize_kernel<<<blocks, TPB>>>(Xs, bins, out, n);
}

// round 3
// speedup vs baseline: 1.2409x; 1.0427x over previous
#include <cuda_runtime.h>
#include <cuda_bf16.h>

#define NBINS 64
#define TPB   256
#define QPT   2           // float4 quads per thread -> 8 elements/thread
#define EPS   2.5e-4f     // edge window in u-units (fast-path u error ~4e-5)

// out[i] = bins[ clip(searchsorted_right(bins, max(logit(x), bins[0])) - 1, 0, 63) ]
// bins = linspace(-6, 6, 64): uniform, step 12/63.
//   u = (log(x)-log(1-x) + 6) * 63/12 = (lg2(x)-lg2(1-x)) * (ln2*5.25) + 31.5
//   idx = clamp(floor(u), 0, 63);  out = idx * (12/63) - 6
// Elements with frac(u) within EPS of an integer boundary are recomputed
// exactly (libdevice logf + searchsorted fixup against the real bins array).

__device__ __forceinline__ float slow_val(float x, const float* __restrict__ bins) {
    float s    = logf(x) - logf(1.0f - x);
    float sbar = fmaxf(s, __ldg(bins));
    float uu   = (sbar + 6.0f) * (63.0f / 12.0f);
    int i = (int)floorf(uu);
    i = i < 0 ? 0 : (i > 63 ? 63 : i);
    if (sbar < __ldg(bins + i))                      i -= 1;
    else if (i < 63 && sbar >= __ldg(bins + i + 1))  i += 1;
    return __ldg(bins + i);
}

__device__ __forceinline__ float fast_u(float x) {
    const float KU = 0.6931471805599453f * 5.25f;   // ln2 * 63/12
    return fmaf(__log2f(x) - __log2f(1.0f - x), KU, 31.5f);
}

__global__ __launch_bounds__(TPB)
void logodds_discretize_kernel(const float* __restrict__ Xs,
                               const float* __restrict__ bins,
                               float* __restrict__ out,
                               int n) {
    const float STEP = 12.0f / 63.0f;

    const float4* X4 = reinterpret_cast<const float4*>(Xs);
    float4*       O4 = reinterpret_cast<float4*>(out);
    int n4 = n >> 2;

    int i0 = blockIdx.x * (TPB * QPT) + threadIdx.x;
    int i1 = i0 + TPB;
    bool v0 = i0 < n4;
    bool v1 = i1 < n4;

    float4 a = make_float4(0.5f, 0.5f, 0.5f, 0.5f);
    float4 b = a;
    if (v0) a = X4[i0];          // front-batched loads (MLP=2)
    if (v1) b = X4[i1];

    float xs[8] = {a.x, a.y, a.z, a.w, b.x, b.y, b.z, b.w};
    float vs[8];
    float maxd = 0.0f;

    #pragma unroll
    for (int e = 0; e < 8; e++) {
        float u    = fast_u(xs[e]);
        float fu   = floorf(u);
        float frac = u - fu;
        maxd = fmaxf(maxd, fabsf(frac - 0.5f));
        float idxf = fminf(fmaxf(fu, 0.0f), 63.0f);
        vs[e] = fmaf(idxf, STEP, -6.0f);
    }

    // Rare per-thread slow path: re-test each element, fix only offenders.
    if (maxd >= 0.5f - EPS) {
        #pragma unroll
        for (int e = 0; e < 8; e++) {
            float u    = fast_u(xs[e]);
            float frac = u - floorf(u);
            if (fabsf(frac - 0.5f) >= 0.5f - EPS)
                vs[e] = slow_val(xs[e], bins);
        }
    }

    if (v0) O4[i0] = make_float4(vs[0], vs[1], vs[2], vs[3]);
    if (v1) O4[i1] = make_float4(vs[4], vs[5], vs[6], vs[7]);

    // scalar tail (n % 4)
    int tail_start = n4 << 2;
    int trem = n - tail_start;
    if (blockIdx.x == 0 && (int)threadIdx.x < trem) {
        int t = tail_start + threadIdx.x;
        float x = Xs[t];
        float u = fast_u(x);
        float fu = floorf(u);
        float frac = u - fu;
        float idxf = fminf(fmaxf(fu, 0.0f), 63.0f);
        float v = fmaf(idxf, STEP, -6.0f);
        if (fabsf(frac - 0.5f) >= 0.5f - EPS) v = slow_val(x, bins);
        out[t] = v;
    }
}

extern "C" void kernel_launch(void* const* d_in, const int* in_sizes, int n_in,
                              void* d_out, int out_size) {
    const float* Xs   = (const float*)d_in[0];
    const float* bins = (const float*)d_in[1];
    float* out        = (float*)d_out;
    int n = in_sizes[0];

    int n4      = n >> 2;
    int per_blk = TPB * QPT;
    int blocks  = (n4 + per_blk - 1) / per_blk;
    if (blocks < 1) blocks = 1;

    logodds_discretize_kernel<<<blocks, TPB>>>(Xs, bins, out, n);
}